// round 17
// baseline (speedup 1.0000x reference)
#include <cuda_runtime.h>
#include <cuda_bf16.h>
#include <cstdint>

#define DMm  1024
#define Hh   16
#define Dd   64
#define Bb   2
#define Ss   2048
#define NTOK (Bb*Ss)   // 4096

#define EXSCALE  0.1803368801111601f
#define MASKMUL  (-1.4426950408889634e9f)

// ---------------------------------------------------------------------------
// Static device scratch
// ---------------------------------------------------------------------------
__device__ float g_SUM[(size_t)Bb*Hh*Ss];
__device__ __nv_bfloat16 g_Xhi [(size_t)3*NTOK*DMm];   // slot 0 reused for O
__device__ __nv_bfloat16 g_Xlo [(size_t)3*NTOK*DMm];
__device__ __nv_bfloat16 g_WThi[(size_t)4*DMm*DMm];
__device__ __nv_bfloat16 g_WTlo[(size_t)4*DMm*DMm];
__device__ __nv_bfloat16 g_Qhi[(size_t)Bb*Hh*Ss*Dd];
__device__ __nv_bfloat16 g_Qlo[(size_t)Bb*Hh*Ss*Dd];
__device__ __nv_bfloat16 g_Khi[(size_t)Bb*Hh*Ss*Dd];
__device__ __nv_bfloat16 g_Klo[(size_t)Bb*Hh*Ss*Dd];
__device__ __nv_bfloat16 g_Vhi[(size_t)Bb*Hh*Ss*Dd];
__device__ __nv_bfloat16 g_Vlo[(size_t)Bb*Hh*Ss*Dd];

// ---------------------------------------------------------------------------
// Helpers
// ---------------------------------------------------------------------------
__device__ __forceinline__ uint32_t smem_u32(const void* p) {
    uint32_t a;
    asm("{ .reg .u64 t; cvta.to.shared.u64 t, %1; cvt.u32.u64 %0, t; }"
        : "=r"(a) : "l"(p));
    return a;
}

__device__ __forceinline__ void ldsm_x4(uint32_t* r, uint32_t addr) {
    asm volatile("ldmatrix.sync.aligned.m8n8.x4.shared.b16 {%0,%1,%2,%3}, [%4];"
        : "=r"(r[0]), "=r"(r[1]), "=r"(r[2]), "=r"(r[3]) : "r"(addr));
}

__device__ __forceinline__ void ldsm_x4_t(uint32_t* r, uint32_t addr) {
    asm volatile("ldmatrix.sync.aligned.m8n8.x4.trans.shared.b16 {%0,%1,%2,%3}, [%4];"
        : "=r"(r[0]), "=r"(r[1]), "=r"(r[2]), "=r"(r[3]) : "r"(addr));
}

__device__ __forceinline__ void mma16816(float* c, const uint32_t* a, const uint32_t* b) {
    asm volatile(
        "mma.sync.aligned.m16n8k16.row.col.f32.bf16.bf16.f32 "
        "{%0,%1,%2,%3}, {%4,%5,%6,%7}, {%8,%9}, {%0,%1,%2,%3};"
        : "+f"(c[0]), "+f"(c[1]), "+f"(c[2]), "+f"(c[3])
        : "r"(a[0]), "r"(a[1]), "r"(a[2]), "r"(a[3]), "r"(b[0]), "r"(b[1]));
}

#define CP_ASYNC16(dst, src) \
    asm volatile("cp.async.cg.shared.global [%0], [%1], 16;" \
        :: "r"(dst), "l"(src))
#define CP_COMMIT() asm volatile("cp.async.commit_group;")
#define CP_WAIT0()  asm volatile("cp.async.wait_group 0;")

__device__ __forceinline__ float ex2f(float x) {
    float r;
    asm("ex2.approx.f32 %0, %1;" : "=f"(r) : "f"(x));
    return r;
}

__device__ __forceinline__ float lg2f(float x) {
    float r;
    asm("lg2.approx.f32 %0, %1;" : "=f"(r) : "f"(x));
    return r;
}

__device__ __forceinline__ ushort bfu(__nv_bfloat16 h) {
    return __bfloat16_as_ushort(h);
}

__device__ __forceinline__ void split4(float4 v, uint2& hi, uint2& lo) {
    __nv_bfloat16 h0 = __float2bfloat16_rn(v.x);
    __nv_bfloat16 h1 = __float2bfloat16_rn(v.y);
    __nv_bfloat16 h2 = __float2bfloat16_rn(v.z);
    __nv_bfloat16 h3 = __float2bfloat16_rn(v.w);
    hi.x = (uint32_t)bfu(h0) | ((uint32_t)bfu(h1) << 16);
    hi.y = (uint32_t)bfu(h2) | ((uint32_t)bfu(h3) << 16);
    __nv_bfloat16 l0 = __float2bfloat16_rn(v.x - __bfloat162float(h0));
    __nv_bfloat16 l1 = __float2bfloat16_rn(v.y - __bfloat162float(h1));
    __nv_bfloat16 l2 = __float2bfloat16_rn(v.z - __bfloat162float(h2));
    __nv_bfloat16 l3 = __float2bfloat16_rn(v.w - __bfloat162float(h3));
    lo.x = (uint32_t)bfu(l0) | ((uint32_t)bfu(l1) << 16);
    lo.y = (uint32_t)bfu(l2) | ((uint32_t)bfu(l3) << 16);
}

__device__ __forceinline__ void pack2(float a, float b, uint32_t& hi, uint32_t& lo) {
    uint32_t u;
    asm("cvt.rn.bf16x2.f32 %0, %1, %2;" : "=r"(u) : "f"(b), "f"(a));
    float af = __uint_as_float(u << 16);
    float bf = __uint_as_float(u & 0xffff0000u);
    hi = u;
    float ra = a - af, rb = b - bf;
    asm("cvt.rn.bf16x2.f32 %0, %1, %2;" : "=r"(lo) : "f"(rb), "f"(ra));
}

// ---------------------------------------------------------------------------
// Fused prep
// ---------------------------------------------------------------------------
__global__ __launch_bounds__(256) void prep_kernel(
    const float* __restrict__ xq, const float* __restrict__ xk,
    const float* __restrict__ xv,
    const float* __restrict__ Wq, const float* __restrict__ Wk,
    const float* __restrict__ Wv, const float* __restrict__ Wo)
{
    __shared__ float t[32][33];
    int bx = blockIdx.x;
    int tid = threadIdx.x;

    if (bx < 12288) {
        int z = bx >> 12;
        int bxx = bx & 4095;
        const float* X = (z == 0) ? xq : (z == 1) ? xk : xv;
        size_t slot = (size_t)z * NTOK * DMm;
        size_t i = ((size_t)bxx * 256 + tid) * 4;
        float4 v = *(const float4*)(X + i);
        uint2 hi, lo;
        split4(v, hi, lo);
        *(uint2*)(g_Xhi + slot + i) = hi;
        *(uint2*)(g_Xlo + slot + i) = lo;
    } else {
        int r = bx - 12288;
        int z = r >> 10;
        int tt = r & 1023;
        int bxw = tt & 31, byw = tt >> 5;
        const float* W = (z == 0) ? Wq : (z == 1) ? Wk : (z == 2) ? Wv : Wo;
        size_t slot = (size_t)z * DMm * DMm;
        int nx = bxw * 32, ky = byw * 32;
        int txx = tid & 31, tyy = tid >> 5;
#pragma unroll
        for (int j = 0; j < 4; j++)
            t[tyy + j*8][txx] = W[(size_t)(ky + tyy + j*8)*DMm + nx + txx];
        __syncthreads();
#pragma unroll
        for (int j = 0; j < 4; j++) {
            float val = t[txx][tyy + j*8];
            __nv_bfloat16 h = __float2bfloat16_rn(val);
            size_t o = slot + (size_t)(nx + tyy + j*8)*DMm + ky + txx;
            g_WThi[o] = h;
            g_WTlo[o] = __float2bfloat16_rn(val - __bfloat162float(h));
        }
    }
}

// ---------------------------------------------------------------------------
// HMMA projection GEMM, cp.async double-buffered; smem-staged coalesced
// epilogue (reuses the free stage buffers after the main loop).
// ---------------------------------------------------------------------------
#define PRS    80
#define P_AHI  0
#define P_ALO  10240
#define P_BHI  20480
#define P_BLO  30720
#define P_SSTR 40960
#define PROJ_SMEM (2*P_SSTR)         // 81920
// epilogue staging (overlaid on the stage buffers):
#define EP_BF_RS   272               // bf16 tile row stride (bytes), 16B-aligned
#define EP_BF_LO   34816             // lo plane offset (128*272)
#define EP_F_RS    528               // fp32 tile row stride (bytes)

__global__ __launch_bounds__(256, 2) void proj_mma_kernel(
    const float* __restrict__ bq, const float* __restrict__ bk,
    const float* __restrict__ bv, float* __restrict__ Yext, int base_mode)
{
    extern __shared__ __align__(16) char psm[];
    uint32_t sb = smem_u32(psm);

    int mode = base_mode + blockIdx.z;
    const float* bias = (blockIdx.z == 0) ? bq : (blockIdx.z == 1) ? bk : bv;

    const __nv_bfloat16* Xhi = g_Xhi + (size_t)(mode == 3 ? 0 : mode) * NTOK * DMm;
    const __nv_bfloat16* Xlo = g_Xlo + (size_t)(mode == 3 ? 0 : mode) * NTOK * DMm;
    const __nv_bfloat16* WThi = g_WThi + (size_t)mode * DMm * DMm;
    const __nv_bfloat16* WTlo = g_WTlo + (size_t)mode * DMm * DMm;

    int tid  = threadIdx.x;
    int lane = tid & 31, wid = tid >> 5;
    int warp_m = wid & 1, warp_n = wid >> 1;
    int row0 = blockIdx.y * 128;
    int col0 = blockIdx.x * 128;

    float acc[4][4][4];
#pragma unroll
    for (int mt = 0; mt < 4; mt++)
#pragma unroll
        for (int nt = 0; nt < 4; nt++)
#pragma unroll
            for (int e = 0; e < 4; e++) acc[mt][nt][e] = 0.f;

    int ld_r = tid >> 1;
    int ld_c = (tid & 1) * 2;

    auto issue = [&](int ch, uint32_t st) {
        int k0 = ch * 32;
#pragma unroll
        for (int cc = 0; cc < 2; cc++) {
            int c = ld_c + cc;
            uint32_t doff = st + (uint32_t)ld_r*PRS + c*16;
            size_t ga = (size_t)(row0 + ld_r)*DMm + k0 + c*8;
            CP_ASYNC16(sb + P_AHI + doff, Xhi + ga);
            CP_ASYNC16(sb + P_ALO + doff, Xlo + ga);
            size_t gb = (size_t)(col0 + ld_r)*DMm + k0 + c*8;
            CP_ASYNC16(sb + P_BHI + doff, WThi + gb);
            CP_ASYNC16(sb + P_BLO + doff, WTlo + gb);
        }
        CP_COMMIT();
    };

    issue(0, 0);

    int a_row = lane & 15;
    int a_kb  = (lane >> 4) * 16;
    int b_row = (lane & 7) + ((lane >> 4) << 3);
    int b_kb  = ((lane >> 3) & 1) * 16;

    for (int ch = 0; ch < 32; ch++) {
        uint32_t st = (uint32_t)(ch & 1) * P_SSTR;
        CP_WAIT0();
        __syncthreads();
        if (ch + 1 < 32)
            issue(ch + 1, (uint32_t)((ch + 1) & 1) * P_SSTR);

#pragma unroll
        for (int kk = 0; kk < 2; kk++) {
            int kbyte = kk * 32;
            uint32_t bhi[4][2], blo[4][2];

#pragma unroll
            for (int p = 0; p < 2; p++) {
                uint32_t bd = sb + st + P_BHI
                            + (uint32_t)(warp_n*32 + p*16 + b_row)*PRS + kbyte + b_kb;
                uint32_t t[4];
                ldsm_x4(t, bd);
                bhi[2*p][0] = t[0]; bhi[2*p][1] = t[1];
                bhi[2*p+1][0] = t[2]; bhi[2*p+1][1] = t[3];
                ldsm_x4(t, bd + (P_BLO - P_BHI));
                blo[2*p][0] = t[0]; blo[2*p][1] = t[1];
                blo[2*p+1][0] = t[2]; blo[2*p+1][1] = t[3];
            }

#pragma unroll
            for (int mt = 0; mt < 4; mt++) {
                uint32_t ahi[4], alo[4];
                uint32_t ad = sb + st + P_AHI
                            + (uint32_t)(warp_m*64 + mt*16 + a_row)*PRS + kbyte + a_kb;
                ldsm_x4(ahi, ad);
                ldsm_x4(alo, ad + (P_ALO - P_AHI));
#pragma unroll
                for (int nt = 0; nt < 4; nt++) {
                    mma16816(acc[mt][nt], ahi, bhi[nt]);
                    mma16816(acc[mt][nt], alo, bhi[nt]);
                    mma16816(acc[mt][nt], ahi, blo[nt]);
                }
            }
        }
        __syncthreads();
    }

    // ---- staged, coalesced epilogue (stage buffers are free now) ----
    int tg = lane >> 2, t4 = lane & 3;

    if (mode == 3) {
        // fp32 tile: rows of 528B (132 floats), conflict-free, 16B-aligned
        float* so = (float*)psm;
#pragma unroll
        for (int mt = 0; mt < 4; mt++) {
            int rl = warp_m*64 + mt*16 + tg;
#pragma unroll
            for (int nt = 0; nt < 4; nt++) {
                int cl = warp_n*32 + nt*8 + t4*2;
                float b0 = bias[col0 + cl], b1 = bias[col0 + cl + 1];
#pragma unroll
                for (int half = 0; half < 2; half++) {
                    int r = rl + half*8;
                    so[(size_t)r*132 + cl]     = acc[mt][nt][half*2 + 0] + b0;
                    so[(size_t)r*132 + cl + 1] = acc[mt][nt][half*2 + 1] + b1;
                }
            }
        }
        __syncthreads();
        int row = tid >> 1, seg = tid & 1;          // 256B halves of a 512B row
#pragma unroll
        for (int i = 0; i < 16; i++) {
            int c4 = seg*64 + i*4;
            float4 v = *(float4*)&so[(size_t)row*132 + c4];
            *(float4*)(Yext + (size_t)(row0 + row)*DMm + col0 + c4) = v;
        }
    } else {
        // bf16 hi/lo tiles: rows of 272B, conflict-free, 16B-aligned
        __nv_bfloat16 *Yhi, *Ylo;
        if (mode == 0) { Yhi = g_Qhi; Ylo = g_Qlo; }
        else if (mode == 1) { Yhi = g_Khi; Ylo = g_Klo; }
        else { Yhi = g_Vhi; Ylo = g_Vlo; }

#pragma unroll
        for (int mt = 0; mt < 4; mt++) {
            int rl = warp_m*64 + mt*16 + tg;
#pragma unroll
            for (int nt = 0; nt < 4; nt++) {
                int cl = warp_n*32 + nt*8 + t4*2;
                float b0 = bias[col0 + cl], b1 = bias[col0 + cl + 1];
#pragma unroll
                for (int half = 0; half < 2; half++) {
                    int r = rl + half*8;
                    uint32_t hi, lo;
                    pack2(acc[mt][nt][half*2 + 0] + b0,
                          acc[mt][nt][half*2 + 1] + b1, hi, lo);
                    *(uint32_t*)(psm + (size_t)r*EP_BF_RS + cl*2)             = hi;
                    *(uint32_t*)(psm + EP_BF_LO + (size_t)r*EP_BF_RS + cl*2)  = lo;
                }
            }
        }
        __syncthreads();
        int row = tid >> 1, piece = tid & 1;        // piece = head half of tile
        int r = row0 + row;
        int bi = r >> 11, s = r & (Ss - 1);
        int hh = (col0 + piece*64) >> 6;
        size_t go = (((size_t)bi*Hh + hh)*Ss + s)*Dd;
#pragma unroll
        for (int i = 0; i < 8; i++) {
            size_t sof = (size_t)row*EP_BF_RS + piece*128 + i*16;
            *(uint4*)(Yhi + go + i*8) = *(uint4*)(psm + sof);
            *(uint4*)(Ylo + go + i*8) = *(uint4*)(psm + EP_BF_LO + sof);
        }
    }
}

// ---------------------------------------------------------------------------
// Attention smem layouts.
// ---------------------------------------------------------------------------
#define RS    144
#define S1QHI   0
#define S1KSTG  18432
#define S1KSTR  9216
#define S1MSK   36864
#define SUM_SMEM (S1MSK + 8192)        // 45056
#define SQHI    0
#define SQLO    18432
#define S2STG   36864
#define S2STR   27648
#define S2KHI   0
#define S2VHI   9216
#define S2VLO   18432
#define S2PS    92160
#define PV_SMEM (S2PS + 18432)         // 110592

#define LOAD_TILE_128(SRC, SOFF)                                             \
    _Pragma("unroll")                                                        \
    for (int i = 0; i < 4; i++) {                                            \
        int f = tid + i*256;                                                 \
        int row = f >> 3, c8 = (f & 7) * 8;                                  \
        *(uint4*)(sm + (SOFF) + row*RS + c8*2) =                             \
            *(const uint4*)((SRC) + (size_t)row*Dd + c8);                    \
    }

// ---------------------------------------------------------------------------
// Pass 1: rowsums of exp(QK^T/8 + mask), HI-ONLY QK.
// ---------------------------------------------------------------------------
__global__ __launch_bounds__(256, 3) void attn_sum_mma(const float* __restrict__ mask)
{
    extern __shared__ __align__(16) char sm[];
    uint32_t sb = smem_u32(sm);
    float* smask = (float*)(sm + S1MSK);

    int tid  = threadIdx.x;
    int lane = tid & 31, w = tid >> 5;
    int tg = lane >> 2, t4 = lane & 3;
    int qt = blockIdx.x, h = blockIdx.y, b = blockIdx.z;

    size_t hb = ((size_t)b*Hh + h)*Ss;
    const __nv_bfloat16* Qh = g_Qhi + (hb + (size_t)qt*128)*Dd;
    const __nv_bfloat16* Kh = g_Khi + hb*Dd;

#pragma unroll
    for (int i = 0; i < 2; i++) {
        int f = tid + i*256;
        *(float4*)&smask[f*4] = *(const float4*)(mask + (size_t)b*Ss + f*4);
    }
    LOAD_TILE_128(Qh, S1QHI)

    int ld_row = tid >> 3, ld_c8 = (tid & 7) * 8;
    auto issue_k = [&](int kt, uint32_t stg) {
#pragma unroll
        for (int i = 0; i < 2; i++) {
            int row = ld_row + i*32;
            uint32_t doff = stg + (uint32_t)row*RS + ld_c8*2;
            CP_ASYNC16(sb + doff, Kh + (size_t)(kt + row)*Dd + ld_c8);
        }
        CP_COMMIT();
    };

    issue_k(0, S1KSTG);
    __syncthreads();

    int a_row = lane & 15;
    int a_kb  = (lane >> 4) * 16;
    int b_row = (lane & 7) + ((lane >> 4) << 3);
    int b_kb  = ((lane >> 3) & 1) * 16;

    float rs0 = 0.f, rs1 = 0.f;

    for (int kt = 0; kt < Ss; kt += 64) {
        uint32_t stg = S1KSTG + (uint32_t)((kt >> 6) & 1) * S1KSTR;
        CP_WAIT0();
        __syncthreads();
        if (kt + 64 < Ss)
            issue_k(kt + 64, S1KSTG + (uint32_t)(((kt >> 6) + 1) & 1) * S1KSTR);

#pragma unroll
        for (int nbp = 0; nbp < 2; nbp++) {
            float accS[4][4];
#pragma unroll
            for (int j = 0; j < 4; j++)
#pragma unroll
                for (int e = 0; e < 4; e++) accS[j][e] = 0.f;

#pragma unroll
            for (int ks = 0; ks < 4; ks++) {
                uint32_t qh[4];
                uint32_t qa = sb + S1QHI + (uint32_t)(w*16 + a_row)*RS + ks*32 + a_kb;
                ldsm_x4(qh, qa);
#pragma unroll
                for (int nb2 = 0; nb2 < 2; nb2++) {
                    int nb = nbp*2 + nb2;
                    uint32_t th[4];
                    uint32_t ad = sb + stg + (uint32_t)(nb*16 + b_row)*RS + ks*32 + b_kb;
                    ldsm_x4(th, ad);
                    int j0 = nb2*2;
                    mma16816(accS[j0],   qh, th);
                    mma16816(accS[j0+1], qh, th+2);
                }
            }

#pragma unroll
            for (int idx = 0; idx < 4; idx++) {
                int col = (nbp*4 + idx)*8 + t4*2;
                float2 mv = *(float2*)&smask[kt + col];
                float m0 = mv.x * MASKMUL, m1 = mv.y * MASKMUL;
                rs0 += ex2f(fmaf(accS[idx][0], EXSCALE, m0))
                     + ex2f(fmaf(accS[idx][1], EXSCALE, m1));
                rs1 += ex2f(fmaf(accS[idx][2], EXSCALE, m0))
                     + ex2f(fmaf(accS[idx][3], EXSCALE, m1));
            }
        }
        __syncthreads();
    }

    rs0 += __shfl_xor_sync(0xffffffffu, rs0, 1);
    rs0 += __shfl_xor_sync(0xffffffffu, rs0, 2);
    rs1 += __shfl_xor_sync(0xffffffffu, rs1, 1);
    rs1 += __shfl_xor_sync(0xffffffffu, rs1, 2);
    if (t4 == 0) {
        size_t base = hb + (size_t)qt*128;
        g_SUM[base + w*16 + tg]     = rs0;
        g_SUM[base + w*16 + tg + 8] = rs1;
    }
}

// ---------------------------------------------------------------------------
// Pass 2: QK (qh*kh + ql*kh), p = ex2(s*scale + mask + log2(1/sum)),
// attn via staged coalesced rows, O += P V (bf16x3).
// ---------------------------------------------------------------------------
__global__ __launch_bounds__(256, 2) void attn_pv_mma(
    const float* __restrict__ mask, float* __restrict__ attn, int write_attn)
{
    extern __shared__ __align__(16) char sm[];
    uint32_t sb = smem_u32(sm);
    float* Ps = (float*)(sm + S2PS);

    int tid  = threadIdx.x;
    int lane = tid & 31, w = tid >> 5;
    int tg = lane >> 2, t4 = lane & 3;
    int qt = blockIdx.x, h = blockIdx.y, b = blockIdx.z;

    size_t hb = ((size_t)b*Hh + h)*Ss;
    const __nv_bfloat16* Qh = g_Qhi + (hb + (size_t)qt*128)*Dd;
    const __nv_bfloat16* Ql = g_Qlo + (hb + (size_t)qt*128)*Dd;
    const __nv_bfloat16* Kh = g_Khi + hb*Dd;
    const __nv_bfloat16* Vh = g_Vhi + hb*Dd;
    const __nv_bfloat16* Vl = g_Vlo + hb*Dd;
    const float* maskb = mask + (size_t)b*Ss;
    float* attn_base = attn + (hb + (size_t)qt*128)*Ss;

    LOAD_TILE_128(Qh, SQHI)
    LOAD_TILE_128(Ql, SQLO)

    int ld_row = tid >> 3, ld_c8 = (tid & 7) * 8;
    auto issue_kv = [&](int kt, uint32_t stg) {
#pragma unroll
        for (int i = 0; i < 2; i++) {
            int row = ld_row + i*32;
            uint32_t doff = stg + (uint32_t)row*RS + ld_c8*2;
            size_t ga = (size_t)(kt + row)*Dd + ld_c8;
            CP_ASYNC16(sb + doff + S2KHI, Kh + ga);
            CP_ASYNC16(sb + doff + S2VHI, Vh + ga);
            CP_ASYNC16(sb + doff + S2VLO, Vl + ga);
        }
        CP_COMMIT();
    };

    issue_kv(0, S2STG);
    __syncthreads();

    int a_row = lane & 15;
    int a_kb  = (lane >> 4) * 16;
    int b_row = (lane & 7) + ((lane >> 4) << 3);
    int b_kb  = ((lane >> 3) & 1) * 16;
    int v_koff = ((lane >> 3) & 1) * 8 + (lane & 7);
    int v_noff = (lane >> 4) * 8;

    uint32_t qfh[4][4], qfl[4][4];
#pragma unroll
    for (int ks = 0; ks < 4; ks++) {
        uint32_t qa = sb + SQHI + (uint32_t)(w*16 + a_row)*RS + ks*32 + a_kb;
        ldsm_x4(qfh[ks], qa);
        ldsm_x4(qfl[ks], qa + (SQLO - SQHI));
    }

    size_t base = hb + (size_t)qt*128;
    float lr0 = -lg2f(g_SUM[base + w*16 + tg]);
    float lr1 = -lg2f(g_SUM[base + w*16 + tg + 8]);
    int r0g = w*16 + tg;

    float accO[8][4];
#pragma unroll
    for (int nt = 0; nt < 8; nt++)
#pragma unroll
        for (int e = 0; e < 4; e++) accO[nt][e] = 0.f;

    for (int kt = 0; kt < Ss; kt += 64) {
        uint32_t stg = S2STG + (uint32_t)((kt >> 6) & 1) * S2STR;
        CP_WAIT0();
        __syncthreads();
        if (kt + 64 < Ss)
            issue_kv(kt + 64, S2STG + (uint32_t)(((kt >> 6) + 1) & 1) * S2STR);

#pragma unroll
        for (int nbp = 0; nbp < 2; nbp++) {
            float accS[4][4];
#pragma unroll
            for (int j = 0; j < 4; j++)
#pragma unroll
                for (int e = 0; e < 4; e++) accS[j][e] = 0.f;

#pragma unroll
            for (int ks = 0; ks < 4; ks++) {
#pragma unroll
                for (int nb2 = 0; nb2 < 2; nb2++) {
                    int nb = nbp*2 + nb2;
                    uint32_t th[4];
                    uint32_t ad = sb + stg + S2KHI + (uint32_t)(nb*16 + b_row)*RS + ks*32 + b_kb;
                    ldsm_x4(th, ad);
                    int j0 = nb2*2;
                    mma16816(accS[j0],   qfh[ks], th);
                    mma16816(accS[j0],   qfl[ks], th);
                    mma16816(accS[j0+1], qfh[ks], th+2);
                    mma16816(accS[j0+1], qfl[ks], th+2);
                }
            }

            uint32_t ph0[4], ph1[4], pl0[4], pl1[4];
#pragma unroll
            for (int idx = 0; idx < 4; idx++) {
                int lc  = idx*8 + t4*2;
                int col = nbp*32 + lc;
                float2 mv = __ldg((const float2*)(maskb + kt + col));
                float b0r0 = fmaf(mv.x, MASKMUL, lr0);
                float b1r0 = fmaf(mv.y, MASKMUL, lr0);
                float b0r1 = fmaf(mv.x, MASKMUL, lr1);
                float b1r1 = fmaf(mv.y, MASKMUL, lr1);
                float p0 = ex2f(fmaf(accS[idx][0], EXSCALE, b0r0));
                float p1 = ex2f(fmaf(accS[idx][1], EXSCALE, b1r0));
                float p2 = ex2f(fmaf(accS[idx][2], EXSCALE, b0r1));
                float p3 = ex2f(fmaf(accS[idx][3], EXSCALE, b1r1));
                if (write_attn) {
                    *(float2*)&Ps[(size_t)r0g*36 + lc]       = make_float2(p0, p1);
                    *(float2*)&Ps[(size_t)(r0g + 8)*36 + lc] = make_float2(p2, p3);
                }
                pack2(p0, p1, ph0[idx], pl0[idx]);
                pack2(p2, p3, ph1[idx], pl1[idx]);
            }

            if (write_attn) {
                __syncthreads();
#pragma unroll
                for (int i = 0; i < 4; i++) {
                    int row = (tid >> 3) + i*32;
                    int c4  = (tid & 7) * 4;
                    float4 v = *(float4*)&Ps[(size_t)row*36 + c4];
                    *(float4*)&attn_base[(size_t)row*Ss + kt + nbp*32 + c4] = v;
                }
            }

#pragma unroll
            for (int nb2 = 0; nb2 < 2; nb2++) {
                int ksv = nbp*2 + nb2;
                uint32_t ah[4] = {ph0[2*nb2], ph1[2*nb2], ph0[2*nb2+1], ph1[2*nb2+1]};
                uint32_t al[4] = {pl0[2*nb2], pl1[2*nb2], pl0[2*nb2+1], pl1[2*nb2+1]};
#pragma unroll
                for (int vb = 0; vb < 4; vb++) {
                    uint32_t th[4], tl[4];
                    uint32_t ad = sb + stg + S2VHI + (uint32_t)(ksv*16 + v_koff)*RS
                                + (vb*16 + v_noff)*2;
                    ldsm_x4_t(th, ad);
                    ldsm_x4_t(tl, ad + (S2VLO - S2VHI));
                    int nt0 = vb*2;
                    mma16816(accO[nt0],   ah, th);
                    mma16816(accO[nt0],   al, th);
                    mma16816(accO[nt0],   ah, tl);
                    mma16816(accO[nt0+1], ah, th+2);
                    mma16816(accO[nt0+1], al, th+2);
                    mma16816(accO[nt0+1], ah, tl+2);
                }
            }
            // Ps reuse barrier only needed before nbp=1's STS; nbp=1's reads
            // are ordered by the tile-end barrier below.
            if (write_attn && nbp == 0)
                __syncthreads();
        }
        __syncthreads();
    }

    int q0 = qt*128 + w*16 + tg;
#pragma unroll
    for (int nt = 0; nt < 8; nt++) {
        int d = nt*8 + t4*2;
        size_t off0 = ((size_t)b*Ss + q0)*DMm + h*64 + d;
        size_t off1 = ((size_t)b*Ss + q0 + 8)*DMm + h*64 + d;
        uint32_t hi, lo;
        pack2(accO[nt][0], accO[nt][1], hi, lo);
        *(uint32_t*)(g_Xhi + off0) = hi;
        *(uint32_t*)(g_Xlo + off0) = lo;
        pack2(accO[nt][2], accO[nt][3], hi, lo);
        *(uint32_t*)(g_Xhi + off1) = hi;
        *(uint32_t*)(g_Xlo + off1) = lo;
    }
}

// ---------------------------------------------------------------------------
// Launch
// ---------------------------------------------------------------------------
extern "C" void kernel_launch(void* const* d_in, const int* in_sizes, int n_in,
                              void* d_out, int out_size)
{
    const float* q    = (const float*)d_in[0];
    const float* k    = (const float*)d_in[1];
    const float* v    = (const float*)d_in[2];
    const float* mask = (const float*)d_in[3];
    const float* Wq   = (const float*)d_in[4];
    const float* bq   = (const float*)d_in[5];
    const float* Wk   = (const float*)d_in[6];
    const float* bk   = (const float*)d_in[7];
    const float* Wv   = (const float*)d_in[8];
    const float* bv   = (const float*)d_in[9];
    const float* Wo   = (const float*)d_in[10];
    const float* bo   = (const float*)d_in[11];

    float* out  = (float*)d_out;
    float* attn = out + (size_t)NTOK*DMm;

    long long need = (long long)NTOK*DMm + (long long)Bb*Hh*Ss*Ss;
    int write_attn = ((long long)out_size >= need) ? 1 : 0;

    cudaFuncSetAttribute(proj_mma_kernel,
                         cudaFuncAttributeMaxDynamicSharedMemorySize, PROJ_SMEM);
    cudaFuncSetAttribute(attn_sum_mma,
                         cudaFuncAttributeMaxDynamicSharedMemorySize, SUM_SMEM);
    cudaFuncSetAttribute(attn_pv_mma,
                         cudaFuncAttributeMaxDynamicSharedMemorySize, PV_SMEM);

    prep_kernel<<<16384, 256>>>(q, k, v, Wq, Wk, Wv, Wo);

    dim3 ggrid3(DMm/128, NTOK/128, 3);
    proj_mma_kernel<<<ggrid3, 256, PROJ_SMEM>>>(bq, bk, bv, nullptr, 0);

    dim3 agrid(Ss/128, Hh, Bb);
    attn_sum_mma<<<agrid, 256, SUM_SMEM>>>(mask);
    attn_pv_mma<<<agrid, 256, PV_SMEM>>>(mask, attn, write_attn);

    dim3 ggrid1(DMm/128, NTOK/128, 1);
    proj_mma_kernel<<<ggrid1, 256, PROJ_SMEM>>>(bo, bo, bo, out, 3);
}